// round 4
// baseline (speedup 1.0000x reference)
#include <cuda_runtime.h>

// LIF neuron scan over time, fused across T in registers.
// x: [T=4, N] fp32, out: [T=4, N] fp32 binary spikes.
// u_t = u_{t-1}*DECAY + x_t ; s_t = (u_t > V_TH) ; u_t = s_t ? 0 : u_t
// Pure streaming, HBM-bound. R1 structure (occ ~79%, regs 32) + streaming stores.

#define LIF_DECAY 0.25f
#define LIF_VTH   1.0f

__global__ __launch_bounds__(256, 8) void lif_kernel(
    const float4* __restrict__ x,
    float4* __restrict__ out,
    int n4)  // float4 lanes per timestep
{
    int i = blockIdx.x * blockDim.x + threadIdx.x;
    if (i >= n4) return;

    // Front-batch all 4 independent loads (MLP=4/thread, ~50 warps/SM).
    float4 x0 = x[i];
    float4 x1 = x[n4 + i];
    float4 x2 = x[2 * n4 + i];
    float4 x3 = x[3 * n4 + i];

    float4 u = make_float4(0.f, 0.f, 0.f, 0.f);
    float4 s;

#define LIF_STEP(XT)                                               \
    do {                                                           \
        u.x = fmaf(u.x, LIF_DECAY, (XT).x);                        \
        u.y = fmaf(u.y, LIF_DECAY, (XT).y);                        \
        u.z = fmaf(u.z, LIF_DECAY, (XT).z);                        \
        u.w = fmaf(u.w, LIF_DECAY, (XT).w);                        \
        s.x = (u.x > LIF_VTH) ? 1.0f : 0.0f;                       \
        s.y = (u.y > LIF_VTH) ? 1.0f : 0.0f;                       \
        s.z = (u.z > LIF_VTH) ? 1.0f : 0.0f;                       \
        s.w = (u.w > LIF_VTH) ? 1.0f : 0.0f;                       \
        u.x = fmaf(-s.x, u.x, u.x);                                \
        u.y = fmaf(-s.y, u.y, u.y);                                \
        u.z = fmaf(-s.z, u.z, u.z);                                \
        u.w = fmaf(-s.w, u.w, u.w);                                \
    } while (0)

    LIF_STEP(x0); __stcs(&out[i],          s);
    LIF_STEP(x1); __stcs(&out[n4 + i],     s);
    LIF_STEP(x2); __stcs(&out[2 * n4 + i], s);
    LIF_STEP(x3); __stcs(&out[3 * n4 + i], s);

#undef LIF_STEP
}

extern "C" void kernel_launch(void* const* d_in, const int* in_sizes, int n_in,
                              void* d_out, int out_size)
{
    const float* x = (const float*)d_in[0];
    float* out = (float*)d_out;

    int total = in_sizes[0];      // T * N
    int n = total / 4;            // elements per timestep (T = 4)
    int n4 = n / 4;               // float4 lanes per timestep

    int threads = 256;
    int blocks = (n4 + threads - 1) / threads;
    lif_kernel<<<blocks, threads>>>((const float4*)x, (float4*)out, n4);
}